// round 2
// baseline (speedup 1.0000x reference)
#include <cuda_runtime.h>
#include <math.h>
#include <stddef.h>

#define BATCH 512
#define TT    256
#define IIN   64
#define HH    256
#define BB    4
#define NBLK  (BATCH / BB)   // 128 blocks, 4 batches each

// ---------------- scratch (static device allocations; no cudaMalloc) --------
__device__ float g_wp0[(IIN + HH) * HH * 4];   // packed layer-0 weights [k][j][gate]
__device__ float g_wp1[(HH + HH) * HH * 4];    // packed layer-1 weights
__device__ float g_bias0[4 * HH];              // b_ih0 + b_hh0
__device__ float g_bias1[4 * HH];
__device__ float g_h1[(size_t)BATCH * TT * HH];// layer-0 outputs (input to layer 1), 128 MB
__device__ float g_h2last[BATCH * HH];         // layer-1 output at t = T-1

// ---------------- weight pre-pack -------------------------------------------
// wp[((k * HH) + j) * 4 + g] = (k < KIN) ? w_ih[(g*HH+j)*KIN + k]
//                                        : w_hh[(g*HH+j)*HH  + (k-KIN)]
// so the LSTM kernel reads one float4 (all 4 gates for h-index j at input k)
// with perfectly coalesced LDG.128 across the warp.
__global__ void pack_weights_kernel(const float* __restrict__ w_ih,
                                    const float* __restrict__ w_hh,
                                    const float* __restrict__ b_ih,
                                    const float* __restrict__ b_hh,
                                    float* __restrict__ wp,
                                    float* __restrict__ bp,
                                    int KIN)
{
    const int KTOT = KIN + HH;
    const int n = KTOT * HH * 4;
    for (int idx = blockIdx.x * blockDim.x + threadIdx.x; idx < n;
         idx += gridDim.x * blockDim.x) {
        int g = idx & 3;
        int j = (idx >> 2) & (HH - 1);
        int k = idx >> 10;              // / (HH*4)
        int r = g * HH + j;
        float v = (k < KIN) ? w_ih[r * KIN + k] : w_hh[r * HH + (k - KIN)];
        wp[idx] = v;
    }
    for (int r = blockIdx.x * blockDim.x + threadIdx.x; r < 4 * HH;
         r += gridDim.x * blockDim.x) {
        bp[r] = b_ih[r] + b_hh[r];
    }
}

// ---------------- fused LSTM layer (input projection fused into recurrence) -
// Thread tid owns h-index tid: gate rows {tid, HH+tid, 2HH+tid, 3HH+tid},
// so c/h updates are thread-local. h is shared across the block via smem.
template <int KIN, bool STORE_ALL>
__global__ __launch_bounds__(HH, 1)
void lstm_layer_kernel(const float* __restrict__ xin,  // [BATCH, TT, KIN]
                       const float* __restrict__ wp,   // packed [(KIN+HH)*HH*4]
                       const float* __restrict__ bp,   // [4*HH]
                       float* __restrict__ out)        // STORE_ALL ? [B,T,H] : [B,H]
{
    constexpr int KTOT = KIN + HH;
    __shared__ __align__(16) float sh[BB * KTOT];  // per-batch concat [x_t | h]

    const int tid = threadIdx.x;
    const int b0  = blockIdx.x * BB;

    const float bi = bp[0 * HH + tid];
    const float bf = bp[1 * HH + tid];
    const float bg = bp[2 * HH + tid];
    const float bo = bp[3 * HH + tid];

    float c[BB];
#pragma unroll
    for (int b = 0; b < BB; ++b) c[b] = 0.0f;

    // init: h part = 0, input part = x[t=0]
#pragma unroll
    for (int b = 0; b < BB; ++b) sh[b * KTOT + KIN + tid] = 0.0f;
    for (int i = tid; i < BB * KIN; i += HH) {
        int b = i / KIN, k = i % KIN;
        sh[b * KTOT + k] = xin[(size_t)(b0 + b) * TT * KIN + k];
    }
    __syncthreads();

    const float4* __restrict__ wp4 = (const float4*)wp;

    for (int t = 0; t < TT; ++t) {
        float ai[BB], af[BB], ag[BB], ao[BB];
#pragma unroll
        for (int b = 0; b < BB; ++b) { ai[b] = bi; af[b] = bf; ag[b] = bg; ao[b] = bo; }

#pragma unroll 2
        for (int k4 = 0; k4 < KTOT / 4; ++k4) {
            const float4 w0 = wp4[(k4 * 4 + 0) * HH + tid];
            const float4 w1 = wp4[(k4 * 4 + 1) * HH + tid];
            const float4 w2 = wp4[(k4 * 4 + 2) * HH + tid];
            const float4 w3 = wp4[(k4 * 4 + 3) * HH + tid];
#pragma unroll
            for (int b = 0; b < BB; ++b) {
                const float4 xv = ((const float4*)(sh + b * KTOT))[k4];
                ai[b] += w0.x * xv.x + w1.x * xv.y + w2.x * xv.z + w3.x * xv.w;
                af[b] += w0.y * xv.x + w1.y * xv.y + w2.y * xv.z + w3.y * xv.w;
                ag[b] += w0.z * xv.x + w1.z * xv.y + w2.z * xv.z + w3.z * xv.w;
                ao[b] += w0.w * xv.x + w1.w * xv.y + w2.w * xv.z + w3.w * xv.w;
            }
        }
        __syncthreads();  // all reads of sh done before we overwrite h / x parts

        float hreg[BB];
#pragma unroll
        for (int b = 0; b < BB; ++b) {
            float iv = 1.0f / (1.0f + expf(-ai[b]));
            float fv = 1.0f / (1.0f + expf(-af[b]));
            float gv = tanhf(ag[b]);
            float ov = 1.0f / (1.0f + expf(-ao[b]));
            c[b] = fv * c[b] + iv * gv;
            float hv = ov * tanhf(c[b]);
            hreg[b] = hv;
            sh[b * KTOT + KIN + tid] = hv;
        }

        if (STORE_ALL) {
#pragma unroll
            for (int b = 0; b < BB; ++b)
                out[((size_t)(b0 + b) * TT + t) * HH + tid] = hreg[b];
        } else if (t == TT - 1) {
#pragma unroll
            for (int b = 0; b < BB; ++b)
                out[(size_t)(b0 + b) * HH + tid] = hreg[b];
        }

        if (t + 1 < TT) {
            for (int i = tid; i < BB * KIN; i += HH) {
                int b = i / KIN, k = i % KIN;
                sh[b * KTOT + k] =
                    xin[(size_t)(b0 + b) * TT * KIN + (size_t)(t + 1) * KIN + k];
            }
        }
        __syncthreads();  // new h / x visible to everyone before next dot
    }
}

// ---------------- LayerNorm + exact GELU + linear head ----------------------
__device__ __forceinline__ float block_sum_256(float v, float* red)
{
    __syncthreads();  // protect red reuse across successive calls
#pragma unroll
    for (int o = 16; o > 0; o >>= 1) v += __shfl_down_sync(0xffffffffu, v, o);
    if ((threadIdx.x & 31) == 0) red[threadIdx.x >> 5] = v;
    __syncthreads();
    if (threadIdx.x < 8) {
        v = red[threadIdx.x];
#pragma unroll
        for (int o = 4; o > 0; o >>= 1) v += __shfl_down_sync(0xffu, v, o);
        if (threadIdx.x == 0) red[0] = v;
    }
    __syncthreads();
    return red[0];
}

__global__ __launch_bounds__(HH)
void head_kernel(const float* __restrict__ h2,     // [BATCH, HH]
                 const float* __restrict__ gamma,
                 const float* __restrict__ beta,
                 const float* __restrict__ hw,     // [1, HH]
                 const float* __restrict__ hb,     // [1]
                 float* __restrict__ outp)         // [BATCH]
{
    __shared__ float red[8];
    const int b = blockIdx.x;
    const int tid = threadIdx.x;

    float v  = h2[(size_t)b * HH + tid];
    float mu = block_sum_256(v, red) * (1.0f / HH);
    float d  = v - mu;
    float var = block_sum_256(d * d, red) * (1.0f / HH);
    float y  = d * rsqrtf(var + 1e-5f) * gamma[tid] + beta[tid];
    // exact GELU: 0.5*y*(1+erf(y/sqrt(2)))
    float gl = 0.5f * y * (1.0f + erff(y * 0.70710678118654752440f));
    float s  = block_sum_256(gl * hw[tid], red);
    if (tid == 0) outp[b] = s + hb[0];
}

// ---------------- launch ----------------------------------------------------
extern "C" void kernel_launch(void* const* d_in, const int* in_sizes, int n_in,
                              void* d_out, int out_size)
{
    (void)in_sizes; (void)n_in; (void)out_size;

    const float* x     = (const float*)d_in[0];
    const float* w_ih0 = (const float*)d_in[1];
    const float* w_hh0 = (const float*)d_in[2];
    const float* b_ih0 = (const float*)d_in[3];
    const float* b_hh0 = (const float*)d_in[4];
    const float* w_ih1 = (const float*)d_in[5];
    const float* w_hh1 = (const float*)d_in[6];
    const float* b_ih1 = (const float*)d_in[7];
    const float* b_hh1 = (const float*)d_in[8];
    const float* ln_g  = (const float*)d_in[9];
    const float* ln_b  = (const float*)d_in[10];
    const float* hw    = (const float*)d_in[11];
    const float* hb    = (const float*)d_in[12];
    float* outp = (float*)d_out;

    float *wp0, *wp1, *bp0, *bp1, *h1, *h2l;
    cudaGetSymbolAddress((void**)&wp0, g_wp0);
    cudaGetSymbolAddress((void**)&wp1, g_wp1);
    cudaGetSymbolAddress((void**)&bp0, g_bias0);
    cudaGetSymbolAddress((void**)&bp1, g_bias1);
    cudaGetSymbolAddress((void**)&h1,  g_h1);
    cudaGetSymbolAddress((void**)&h2l, g_h2last);

    pack_weights_kernel<<<512, 256>>>(w_ih0, w_hh0, b_ih0, b_hh0, wp0, bp0, IIN);
    pack_weights_kernel<<<512, 256>>>(w_ih1, w_hh1, b_ih1, b_hh1, wp1, bp1, HH);

    lstm_layer_kernel<IIN, true ><<<NBLK, HH>>>(x,  wp0, bp0, h1);
    lstm_layer_kernel<HH,  false><<<NBLK, HH>>>(h1, wp1, bp1, h2l);

    head_kernel<<<BATCH, HH>>>(h2l, ln_g, ln_b, hw, hb, outp);
}

// round 4
// speedup vs baseline: 1.3054x; 1.3054x over previous
#include <cuda_runtime.h>
#include <cuda_bf16.h>
#include <mma.h>
#include <math.h>
#include <stddef.h>
#include <stdint.h>

using namespace nvcuda;

#define BATCH 512
#define TT    256
#define IIN   64
#define HH    256
#define BB    4
#define NBLK  (BATCH / BB)          // 128 recurrence CTAs
#define MTOT  (BATCH * TT)          // 131072 rows for x_proj GEMMs

// ---------------- static device scratch ------------------------------------
__device__ __nv_bfloat16 g_xhi[(size_t)MTOT * IIN];
__device__ __nv_bfloat16 g_xlo[(size_t)MTOT * IIN];
__device__ __nv_bfloat16 g_w0hi[4 * HH * IIN];
__device__ __nv_bfloat16 g_w0lo[4 * HH * IIN];
__device__ __nv_bfloat16 g_w1hi[4 * HH * HH];
__device__ __nv_bfloat16 g_w1lo[4 * HH * HH];
__device__ __nv_bfloat16 g_h1hi[(size_t)MTOT * HH];
__device__ __nv_bfloat16 g_h1lo[(size_t)MTOT * HH];
__device__ float g_xp[(size_t)4 * MTOT * HH];     // [4][MTOT][256] gate-major
__device__ float g_wp0[HH * HH * 4];              // packed w_hh [k][j][gate]
__device__ float g_wp1[HH * HH * 4];
__device__ float g_bias0[4 * HH];
__device__ float g_bias1[4 * HH];
__device__ float g_h2last[BATCH * HH];

// ---------------- packed f32x2 helpers (Blackwell FFMA2) --------------------
#define FMA2(acc, w, x) \
    asm("fma.rn.f32x2 %0, %1, %2, %0;" : "+l"(acc) : "l"(w), "l"(x))
#define ADD2(acc, v) \
    asm("add.rn.f32x2 %0, %0, %1;" : "+l"(acc) : "l"(v))

// ---------------- conversions & packing ------------------------------------
__global__ void cvt_pair_kernel(const float* __restrict__ src,
                                __nv_bfloat16* __restrict__ hi,
                                __nv_bfloat16* __restrict__ lo, size_t n)
{
    for (size_t i = (size_t)blockIdx.x * blockDim.x + threadIdx.x; i < n;
         i += (size_t)gridDim.x * blockDim.x) {
        float v = src[i];
        __nv_bfloat16 h = __float2bfloat16(v);
        hi[i] = h;
        lo[i] = __float2bfloat16(v - __bfloat162float(h));
    }
}

__global__ void pack_whh_kernel(const float* __restrict__ w_hh,
                                const float* __restrict__ b_ih,
                                const float* __restrict__ b_hh,
                                float* __restrict__ wp,
                                float* __restrict__ bp)
{
    const int n = HH * HH * 4;
    for (int idx = blockIdx.x * blockDim.x + threadIdx.x; idx < n;
         idx += gridDim.x * blockDim.x) {
        int g = idx & 3;
        int j = (idx >> 2) & (HH - 1);
        int k = idx >> 10;
        wp[idx] = w_hh[(g * HH + j) * HH + k];
    }
    for (int r = blockIdx.x * blockDim.x + threadIdx.x; r < 4 * HH;
         r += gridDim.x * blockDim.x)
        bp[r] = b_ih[r] + b_hh[r];
}

// ---------------- x_proj GEMM on HMMA (wmma, bf16 hi/lo 3-term) --------------
// C[M,1024] = A[M,K] @ B[1024,K]^T, fp32 accum. Scattered to xp[4][MTOT][256].
// CTA tile 128(M) x 128(N); 8 warps in a 4x2 grid, warp tile 32x64.
template <int K>
__global__ __launch_bounds__(256, 1)
void gemm_xproj_wmma(const __nv_bfloat16* __restrict__ Ahi,
                     const __nv_bfloat16* __restrict__ Alo,
                     const __nv_bfloat16* __restrict__ Bhi,
                     const __nv_bfloat16* __restrict__ Blo,
                     float* __restrict__ xp)
{
    const int w  = threadIdx.x >> 5;
    const int wm = w & 3, wn = w >> 2;
    const size_t m0 = (size_t)blockIdx.x * 128 + wm * 32;
    const int    n0 = blockIdx.y * 128 + wn * 64;

    wmma::fragment<wmma::accumulator, 16, 16, 16, float> acc[2][4];
#pragma unroll
    for (int i = 0; i < 2; ++i)
#pragma unroll
        for (int f = 0; f < 4; ++f) wmma::fill_fragment(acc[i][f], 0.0f);

#pragma unroll
    for (int term = 0; term < 3; ++term) {
        const __nv_bfloat16* A = (term == 1) ? Alo : Ahi;
        const __nv_bfloat16* B = (term == 2) ? Blo : Bhi;
#pragma unroll
        for (int k0 = 0; k0 < K; k0 += 16) {
            wmma::fragment<wmma::matrix_a, 16, 16, 16, __nv_bfloat16,
                           wmma::row_major> fa[2];
            wmma::load_matrix_sync(fa[0], A + m0 * K + k0, K);
            wmma::load_matrix_sync(fa[1], A + (m0 + 16) * K + k0, K);
#pragma unroll
            for (int f = 0; f < 4; ++f) {
                wmma::fragment<wmma::matrix_b, 16, 16, 16, __nv_bfloat16,
                               wmma::col_major> fb;
                wmma::load_matrix_sync(fb, B + (size_t)(n0 + f * 16) * K + k0, K);
                wmma::mma_sync(acc[0][f], fa[0], fb, acc[0][f]);
                wmma::mma_sync(acc[1][f], fa[1], fb, acc[1][f]);
            }
        }
    }

#pragma unroll
    for (int i = 0; i < 2; ++i)
#pragma unroll
        for (int f = 0; f < 4; ++f) {
            int c0 = n0 + f * 16;
            int g = c0 >> 8, j0 = c0 & 255;
            float* dst = xp + ((size_t)g * MTOT + m0 + i * 16) * HH + j0;
            wmma::store_matrix_sync(dst, acc[i][f], HH, wmma::mem_row_major);
        }
}

// ---------------- recurrence: split-K, packed FFMA2 --------------------------
// 512 threads: j = tid&255 (hidden index), kh = tid>>8 (K-half).
// Gate pairs (i,f) and (g,o) packed as f32x2; weights [k][j][4] load as
// ulonglong2 giving both packed pairs with zero repack cost. h is stored
// duplicated {h,h} in smem so the x operand is one broadcast LDS.64.
// Each half finalizes 2 of the 4 batches (activations split across halves).
template <bool STORE_PAIR>
__global__ __launch_bounds__(512, 1)
void lstm_rec_kernel(const float* __restrict__ xp,   // [4][MTOT][256]
                     const float* __restrict__ wp,   // [256][256][4]
                     const float* __restrict__ bp,   // [4*256]
                     __nv_bfloat16* __restrict__ ohi,
                     __nv_bfloat16* __restrict__ olo,
                     float* __restrict__ olast)      // [BATCH][HH]
{
    __shared__ __align__(16) unsigned long long shd[HH * BB];      // {h,h} dup
    __shared__ __align__(16) unsigned long long spart[BB * 2 * HH];

    const int tid = threadIdx.x;
    const int j   = tid & (HH - 1);
    const int kh  = tid >> 8;                 // 0 or 1
    const int klo = kh * 128, khi = klo + 128;
    const int bfin = kh * 2;                  // batches this half finalizes
    const int bexp = 2 - kh * 2;              // batches whose partials we export
    const int b0   = blockIdx.x * BB;

    const float bi = bp[0 * HH + j], bf_ = bp[1 * HH + j];
    const float bg = bp[2 * HH + j], bo  = bp[3 * HH + j];

    float c[2] = {0.0f, 0.0f};

    for (int i = tid; i < HH * BB; i += 512) shd[i] = 0ull;
    __syncthreads();

    const ulonglong2* __restrict__ wp2 = (const ulonglong2*)wp;

    for (int t = 0; t < TT; ++t) {
        unsigned long long aif[BB], ago[BB];
#pragma unroll
        for (int b = 0; b < BB; ++b) { aif[b] = 0ull; ago[b] = 0ull; }

#pragma unroll 4
        for (int k = klo; k < khi; ++k) {
            const ulonglong2 wv = wp2[k * HH + j];   // (wi,wf) , (wg,wo)
#pragma unroll
            for (int b = 0; b < BB; ++b) {
                unsigned long long xd = shd[k * BB + b];  // broadcast
                FMA2(aif[b], wv.x, xd);
                FMA2(ago[b], wv.y, xd);
            }
        }

        // export partials for the batches the OTHER half finalizes
#pragma unroll
        for (int bb = 0; bb < 2; ++bb) {
            int b = bexp + bb;
            spart[(b * 2 + 0) * HH + j] = aif[b];
            spart[(b * 2 + 1) * HH + j] = ago[b];
        }
        __syncthreads();

#pragma unroll
        for (int bb = 0; bb < 2; ++bb) {
            int b = bfin + bb;
            unsigned long long vif = aif[b], vgo = ago[b];
            ADD2(vif, spart[(b * 2 + 0) * HH + j]);
            ADD2(vgo, spart[(b * 2 + 1) * HH + j]);
            float vi, vf, vg, vo;
            asm("mov.b64 {%0,%1}, %2;" : "=f"(vi), "=f"(vf) : "l"(vif));
            asm("mov.b64 {%0,%1}, %2;" : "=f"(vg), "=f"(vo) : "l"(vgo));
            const size_t m = (size_t)(b0 + b) * TT + t;
            vi += bi  + xp[((size_t)0 * MTOT + m) * HH + j];
            vf += bf_ + xp[((size_t)1 * MTOT + m) * HH + j];
            vg += bg  + xp[((size_t)2 * MTOT + m) * HH + j];
            vo += bo  + xp[((size_t)3 * MTOT + m) * HH + j];
            float iv = 1.0f / (1.0f + expf(-vi));
            float fv = 1.0f / (1.0f + expf(-vf));
            float gv = tanhf(vg);
            float ov = 1.0f / (1.0f + expf(-vo));
            c[bb] = fv * c[bb] + iv * gv;
            float hv = ov * tanhf(c[bb]);
            unsigned long long hd;
            asm("mov.b64 %0, {%1,%1};" : "=l"(hd) : "f"(hv));
            shd[j * BB + b] = hd;
            if (STORE_PAIR) {
                __nv_bfloat16 h16 = __float2bfloat16(hv);
                ohi[m * HH + j] = h16;
                olo[m * HH + j] = __float2bfloat16(hv - __bfloat162float(h16));
            } else if (t == TT - 1) {
                olast[(size_t)(b0 + b) * HH + j] = hv;
            }
        }
        __syncthreads();
    }
}

// ---------------- LayerNorm + exact GELU + linear head ----------------------
__device__ __forceinline__ float block_sum_256(float v, float* red)
{
    __syncthreads();
#pragma unroll
    for (int o = 16; o > 0; o >>= 1) v += __shfl_down_sync(0xffffffffu, v, o);
    if ((threadIdx.x & 31) == 0) red[threadIdx.x >> 5] = v;
    __syncthreads();
    if (threadIdx.x < 8) {
        v = red[threadIdx.x];
#pragma unroll
        for (int o = 4; o > 0; o >>= 1) v += __shfl_down_sync(0xffu, v, o);
        if (threadIdx.x == 0) red[0] = v;
    }
    __syncthreads();
    return red[0];
}

__global__ __launch_bounds__(HH)
void head_kernel(const float* __restrict__ h2,
                 const float* __restrict__ gamma,
                 const float* __restrict__ beta,
                 const float* __restrict__ hw,
                 const float* __restrict__ hb,
                 float* __restrict__ outp)
{
    __shared__ float red[8];
    const int b = blockIdx.x;
    const int tid = threadIdx.x;

    float v  = h2[(size_t)b * HH + tid];
    float mu = block_sum_256(v, red) * (1.0f / HH);
    float d  = v - mu;
    float var = block_sum_256(d * d, red) * (1.0f / HH);
    float y  = d * rsqrtf(var + 1e-5f) * gamma[tid] + beta[tid];
    float gl = 0.5f * y * (1.0f + erff(y * 0.70710678118654752440f));
    float s  = block_sum_256(gl * hw[tid], red);
    if (tid == 0) outp[b] = s + hb[0];
}

// ---------------- launch ----------------------------------------------------
extern "C" void kernel_launch(void* const* d_in, const int* in_sizes, int n_in,
                              void* d_out, int out_size)
{
    (void)in_sizes; (void)n_in; (void)out_size;

    const float* x     = (const float*)d_in[0];
    const float* w_ih0 = (const float*)d_in[1];
    const float* w_hh0 = (const float*)d_in[2];
    const float* b_ih0 = (const float*)d_in[3];
    const float* b_hh0 = (const float*)d_in[4];
    const float* w_ih1 = (const float*)d_in[5];
    const float* w_hh1 = (const float*)d_in[6];
    const float* b_ih1 = (const float*)d_in[7];
    const float* b_hh1 = (const float*)d_in[8];
    const float* ln_g  = (const float*)d_in[9];
    const float* ln_b  = (const float*)d_in[10];
    const float* hw    = (const float*)d_in[11];
    const float* hb    = (const float*)d_in[12];
    float* outp = (float*)d_out;

    __nv_bfloat16 *xhi, *xlo, *w0hi, *w0lo, *w1hi, *w1lo, *h1hi, *h1lo;
    float *xp, *wp0, *wp1, *bp0, *bp1, *h2l;
    cudaGetSymbolAddress((void**)&xhi,  g_xhi);
    cudaGetSymbolAddress((void**)&xlo,  g_xlo);
    cudaGetSymbolAddress((void**)&w0hi, g_w0hi);
    cudaGetSymbolAddress((void**)&w0lo, g_w0lo);
    cudaGetSymbolAddress((void**)&w1hi, g_w1hi);
    cudaGetSymbolAddress((void**)&w1lo, g_w1lo);
    cudaGetSymbolAddress((void**)&h1hi, g_h1hi);
    cudaGetSymbolAddress((void**)&h1lo, g_h1lo);
    cudaGetSymbolAddress((void**)&xp,   g_xp);
    cudaGetSymbolAddress((void**)&wp0,  g_wp0);
    cudaGetSymbolAddress((void**)&wp1,  g_wp1);
    cudaGetSymbolAddress((void**)&bp0,  g_bias0);
    cudaGetSymbolAddress((void**)&bp1,  g_bias1);
    cudaGetSymbolAddress((void**)&h2l,  g_h2last);

    cvt_pair_kernel<<<512, 256>>>(x,     xhi,  xlo,  (size_t)MTOT * IIN);
    cvt_pair_kernel<<<128, 256>>>(w_ih0, w0hi, w0lo, (size_t)4 * HH * IIN);
    cvt_pair_kernel<<<256, 256>>>(w_ih1, w1hi, w1lo, (size_t)4 * HH * HH);
    pack_whh_kernel<<<256, 256>>>(w_hh0, b_ih0, b_hh0, wp0, bp0);
    pack_whh_kernel<<<256, 256>>>(w_hh1, b_ih1, b_hh1, wp1, bp1);

    // layer 0: x_proj GEMM (K=64) then recurrence (emits h1 as bf16 hi/lo)
    gemm_xproj_wmma<IIN><<<dim3(MTOT / 128, 8), 256>>>(xhi, xlo, w0hi, w0lo, xp);
    lstm_rec_kernel<true><<<NBLK, 512>>>(xp, wp0, bp0, h1hi, h1lo, nullptr);

    // layer 1: x_proj GEMM (K=256) from h1 pair, recurrence keeps last h only
    gemm_xproj_wmma<HH><<<dim3(MTOT / 128, 8), 256>>>(h1hi, h1lo, w1hi, w1lo, xp);
    lstm_rec_kernel<false><<<NBLK, 512>>>(xp, wp1, bp1, nullptr, nullptr, h2l);

    head_kernel<<<BATCH, HH>>>(h2l, ln_g, ln_b, hw, hb, outp);
}